// round 3
// baseline (speedup 1.0000x reference)
#include <cuda_runtime.h>
#include <cuda_bf16.h>
#include <cstdint>
#include <cstddef>

typedef __nv_bfloat16 bf16;
#define DI __device__ __forceinline__

constexpr int Bn = 4, Pn = 1024, Xn = 8192, Cn = 1024;

// ---------------- scratch (device globals, no allocation) ----------------
__device__ bf16  g_qh[(size_t)Bn * Pn * Cn];   // hi(LN(feat)*g+b * 1/32)
__device__ bf16  g_ql[(size_t)Bn * Pn * Cn];   // lo residual
__device__ bf16  g_kh[(size_t)Bn * Xn * Cn];   // hi((LN(mem_k)*g+b) * mem_c)
__device__ bf16  g_kl[(size_t)Bn * Xn * Cn];   // lo residual
__device__ bf16  g_v [(size_t)Bn * Xn * Cn];   // LN(mem_v)*g+b
__device__ bf16  g_vt[(size_t)Bn * Cn * Xn];   // v transposed [b][c][x]
__device__ float g_S [(size_t)Bn * Pn * Xn];   // scores fp32
__device__ bf16  g_W [(size_t)Bn * Pn * Xn];   // renormalized sparse attn

// ---------------- small PTX helpers ----------------
DI void cp_async16(uint32_t saddr, const void* gptr) {
    asm volatile("cp.async.cg.shared.global [%0], [%1], 16;\n" :: "r"(saddr), "l"(gptr));
}
DI void cp_commit() { asm volatile("cp.async.commit_group;\n"); }
template <int N> DI void cp_wait() { asm volatile("cp.async.wait_group %0;\n" :: "n"(N)); }

DI void ldsm4(uint32_t addr, uint32_t& r0, uint32_t& r1, uint32_t& r2, uint32_t& r3) {
    asm volatile("ldmatrix.sync.aligned.m8n8.x4.shared.b16 {%0,%1,%2,%3}, [%4];\n"
                 : "=r"(r0), "=r"(r1), "=r"(r2), "=r"(r3) : "r"(addr));
}
DI void mma16816(float c[4], const uint32_t a[4], const uint32_t b[2]) {
    asm volatile(
        "mma.sync.aligned.m16n8k16.row.col.f32.bf16.bf16.f32 "
        "{%0,%1,%2,%3}, {%4,%5,%6,%7}, {%8,%9}, {%0,%1,%2,%3};\n"
        : "+f"(c[0]), "+f"(c[1]), "+f"(c[2]), "+f"(c[3])
        : "r"(a[0]), "r"(a[1]), "r"(a[2]), "r"(a[3]), "r"(b[0]), "r"(b[1]));
}

// Swizzled byte offset inside a 128-row x 64-col bf16 tile (128B rows, SW128 XOR).
DI uint32_t swz(int r, int c8) { return (uint32_t)(r * 128 + ((c8 ^ (r & 7)) << 4)); }

// ---------------- LayerNorm -> bf16 hi/lo (C = 1024 fixed) ----------------
// y = ((x - mu) * rstd * gamma + beta) * scale ; scale = cscale[row] or sconst
// dst_h = bf16(y), dst_l = bf16(y - dst_h) if dst_l != nullptr
__global__ void __launch_bounds__(256) ln_kernel(
    const float* __restrict__ src, bf16* __restrict__ dst_h, bf16* __restrict__ dst_l,
    const float* __restrict__ gamma, const float* __restrict__ beta,
    const float* __restrict__ cscale, float sconst)
{
    const int row = blockIdx.x;
    const int t = threadIdx.x;
    const float4* s4 = reinterpret_cast<const float4*>(src) + (size_t)row * 256;
    float4 x = s4[t];
    float sum = x.x + x.y + x.z + x.w;
    float sq  = fmaf(x.x, x.x, fmaf(x.y, x.y, fmaf(x.z, x.z, x.w * x.w)));
#pragma unroll
    for (int o = 16; o; o >>= 1) {
        sum += __shfl_xor_sync(0xffffffffu, sum, o);
        sq  += __shfl_xor_sync(0xffffffffu, sq,  o);
    }
    __shared__ float s_sum[8], s_sq[8];
    if ((t & 31) == 0) { s_sum[t >> 5] = sum; s_sq[t >> 5] = sq; }
    __syncthreads();
    sum = 0.f; sq = 0.f;
#pragma unroll
    for (int i = 0; i < 8; i++) { sum += s_sum[i]; sq += s_sq[i]; }
    const float mu  = sum * (1.f / 1024.f);
    const float var = sq * (1.f / 1024.f) - mu * mu;
    const float rs  = rsqrtf(var + 1e-5f);
    const float sc  = cscale ? __ldg(cscale + row) : sconst;

    const float4 g = reinterpret_cast<const float4*>(gamma)[t];
    const float4 b = reinterpret_cast<const float4*>(beta)[t];
    float y[4];
    y[0] = ((x.x - mu) * rs * g.x + b.x) * sc;
    y[1] = ((x.y - mu) * rs * g.y + b.y) * sc;
    y[2] = ((x.z - mu) * rs * g.z + b.z) * sc;
    y[3] = ((x.w - mu) * rs * g.w + b.w) * sc;

    bf16 h[4];
#pragma unroll
    for (int i = 0; i < 4; i++) h[i] = __float2bfloat16(y[i]);
    uint2 pk;
    {
        __nv_bfloat162 lo2 = __nv_bfloat162(h[0], h[1]);
        __nv_bfloat162 hi2 = __nv_bfloat162(h[2], h[3]);
        pk.x = *reinterpret_cast<uint32_t*>(&lo2);
        pk.y = *reinterpret_cast<uint32_t*>(&hi2);
    }
    reinterpret_cast<uint2*>(dst_h + (size_t)row * 1024)[t] = pk;

    if (dst_l) {
        bf16 l[4];
#pragma unroll
        for (int i = 0; i < 4; i++) l[i] = __float2bfloat16(y[i] - __bfloat162float(h[i]));
        uint2 pl;
        __nv_bfloat162 lo2 = __nv_bfloat162(l[0], l[1]);
        __nv_bfloat162 hi2 = __nv_bfloat162(l[2], l[3]);
        pl.x = *reinterpret_cast<uint32_t*>(&lo2);
        pl.y = *reinterpret_cast<uint32_t*>(&hi2);
        reinterpret_cast<uint2*>(dst_l + (size_t)row * 1024)[t] = pl;
    }
}

// ---------------- bf16 transpose: [b][X][C] -> [b][C][X] ----------------
__global__ void transpose_kernel(const bf16* __restrict__ src, bf16* __restrict__ dst)
{
    __shared__ bf16 tile[32][34];
    const int b = blockIdx.z;
    const int x0 = blockIdx.x << 5, c0 = blockIdx.y << 5;
    const bf16* s = src + ((size_t)b * Xn + x0) * Cn + c0;
#pragma unroll
    for (int j = 0; j < 4; j++)
        tile[threadIdx.y + j * 8][threadIdx.x] =
            s[(size_t)(threadIdx.y + j * 8) * Cn + threadIdx.x];
    __syncthreads();
    bf16* d = dst + ((size_t)b * Cn + c0) * Xn + x0;
#pragma unroll
    for (int j = 0; j < 4; j++)
        d[(size_t)(threadIdx.y + j * 8) * Xn + threadIdx.x] =
            tile[threadIdx.x][threadIdx.y + j * 8];
}

// ---------------- tiled bf16 GEMM: C[M,N] = A[M,K] * B[N,K]^T ----------------
// SPLIT=1: emulated-fp32 via 3 bf16 passes: Ah*Bh + Ah*Bl + Al*Bh (K=1024 each).
// EPI 0: store fp32 scores.  EPI 1: store fp32 (acc + Res).
template <int EPI, int SPLIT>
__global__ void __launch_bounds__(256) gemm_kernel(
    const bf16* __restrict__ Ah, const bf16* __restrict__ Al,
    const bf16* __restrict__ Bh, const bf16* __restrict__ Bl,
    float* __restrict__ Co, const float* __restrict__ Res,
    int M, int N, int K)
{
    extern __shared__ __align__(1024) char smem_raw[];
    const int tid = threadIdx.x, lane = tid & 31, warp = tid >> 5;
    const int wm = warp & 3, wn = warp >> 2;         // 4 x 2 warp grid
    const int bN = blockIdx.x, bM = blockIdx.y, bz = blockIdx.z;

    const size_t aoff = (size_t)bz * M * K + (size_t)bM * 128 * K;
    const size_t boff = (size_t)bz * N * K + (size_t)bN * 128 * K;
    Ah += aoff; Bh += boff;
    if (SPLIT) { Al += aoff; Bl += boff; }

    const uint32_t sb  = (uint32_t)__cvta_generic_to_shared(smem_raw);
    const uint32_t sA0 = sb;            // 2 stages x 16KB
    const uint32_t sB0 = sb + 32768;    // 2 stages x 16KB

    const int KT0 = K >> 6;                      // tiles per section
    const int KT  = SPLIT ? 3 * KT0 : KT0;

    auto load_tiles = [&](int kt, int stg) {
        const bf16* As = Ah;
        const bf16* Bs = Bh;
        int k0;
        if (SPLIT) {
            const int sec = kt / KT0;
            k0 = (kt - sec * KT0) * 64;
            if (sec == 1) Bs = Bl;          // qh * kl
            else if (sec == 2) As = Al;     // ql * kh
        } else {
            k0 = kt * 64;
        }
        const uint32_t sa = sA0 + stg * 16384, sbb = sB0 + stg * 16384;
#pragma unroll
        for (int i = 0; i < 4; i++) {
            int idx = tid + i * 256;
            int r = idx >> 3, c8 = idx & 7;
            cp_async16(sa + swz(r, c8), As + (size_t)r * K + k0 + c8 * 8);
        }
#pragma unroll
        for (int i = 0; i < 4; i++) {
            int idx = tid + i * 256;
            int r = idx >> 3, c8 = idx & 7;
            cp_async16(sbb + swz(r, c8), Bs + (size_t)r * K + k0 + c8 * 8);
        }
        cp_commit();
    };

    float acc[2][8][4];
#pragma unroll
    for (int mt = 0; mt < 2; mt++)
#pragma unroll
        for (int nt = 0; nt < 8; nt++)
#pragma unroll
            for (int i = 0; i < 4; i++) acc[mt][nt][i] = 0.f;

    load_tiles(0, 0);

    for (int kt = 0; kt < KT; kt++) {
        const int stg = kt & 1;
        if (kt + 1 < KT) { load_tiles(kt + 1, stg ^ 1); cp_wait<1>(); }
        else             { cp_wait<0>(); }
        __syncthreads();
        const uint32_t sa = sA0 + stg * 16384, sbb = sB0 + stg * 16384;
#pragma unroll
        for (int kk = 0; kk < 4; kk++) {
            uint32_t af[2][4];
#pragma unroll
            for (int mt = 0; mt < 2; mt++) {
                int r = wm * 32 + mt * 16 + (lane & 15);
                int c8 = kk * 2 + (lane >> 4);
                ldsm4(sa + swz(r, c8), af[mt][0], af[mt][1], af[mt][2], af[mt][3]);
            }
            uint32_t bfr[8][2];
#pragma unroll
            for (int np = 0; np < 4; np++) {
                int r = wn * 64 + np * 16 + ((lane >> 4) << 3) + (lane & 7);
                int c8 = kk * 2 + ((lane >> 3) & 1);
                ldsm4(sbb + swz(r, c8), bfr[2 * np][0], bfr[2 * np][1],
                                         bfr[2 * np + 1][0], bfr[2 * np + 1][1]);
            }
#pragma unroll
            for (int mt = 0; mt < 2; mt++)
#pragma unroll
                for (int nt = 0; nt < 8; nt++)
                    mma16816(acc[mt][nt], af[mt], bfr[nt]);
        }
        __syncthreads();
    }

    const int row0 = bM * 128 + wm * 32;
    const int col0 = bN * 128 + wn * 64;
    const int tr = lane >> 2, tc = (lane & 3) << 1;
    float* C0 = Co + (size_t)bz * M * N;
    if (EPI == 0) {
#pragma unroll
        for (int mt = 0; mt < 2; mt++)
#pragma unroll
            for (int nt = 0; nt < 8; nt++) {
                int p = row0 + mt * 16 + tr, x = col0 + nt * 8 + tc;
                *reinterpret_cast<float2*>(C0 + (size_t)p * N + x) =
                    make_float2(acc[mt][nt][0], acc[mt][nt][1]);
                *reinterpret_cast<float2*>(C0 + (size_t)(p + 8) * N + x) =
                    make_float2(acc[mt][nt][2], acc[mt][nt][3]);
            }
    } else {
        const float* R0 = Res + (size_t)bz * M * N;
#pragma unroll
        for (int mt = 0; mt < 2; mt++)
#pragma unroll
            for (int nt = 0; nt < 8; nt++) {
                int p = row0 + mt * 16 + tr, x = col0 + nt * 8 + tc;
                float2 r0 = *reinterpret_cast<const float2*>(R0 + (size_t)p * N + x);
                float2 r1 = *reinterpret_cast<const float2*>(R0 + (size_t)(p + 8) * N + x);
                *reinterpret_cast<float2*>(C0 + (size_t)p * N + x) =
                    make_float2(acc[mt][nt][0] + r0.x, acc[mt][nt][1] + r0.y);
                *reinterpret_cast<float2*>(C0 + (size_t)(p + 8) * N + x) =
                    make_float2(acc[mt][nt][2] + r1.x, acc[mt][nt][3] + r1.y);
            }
    }
}

// ---------------- softmax + threshold + renorm over X=8192 ----------------
DI float blockMax(float v, float* red) {
#pragma unroll
    for (int o = 16; o; o >>= 1) v = fmaxf(v, __shfl_xor_sync(0xffffffffu, v, o));
    __syncthreads();
    if ((threadIdx.x & 31) == 0) red[threadIdx.x >> 5] = v;
    __syncthreads();
    float r = red[0];
#pragma unroll
    for (int i = 1; i < 8; i++) r = fmaxf(r, red[i]);
    return r;
}
DI float blockSum(float v, float* red) {
#pragma unroll
    for (int o = 16; o; o >>= 1) v += __shfl_xor_sync(0xffffffffu, v, o);
    __syncthreads();
    if ((threadIdx.x & 31) == 0) red[threadIdx.x >> 5] = v;
    __syncthreads();
    float r = 0.f;
#pragma unroll
    for (int i = 0; i < 8; i++) r += red[i];
    return r;
}

__global__ void __launch_bounds__(256) softmax_kernel(
    const float* __restrict__ S, bf16* __restrict__ W)
{
    __shared__ float red[8];
    const size_t row = blockIdx.x;
    const int t = threadIdx.x;
    const float4* s4 = reinterpret_cast<const float4*>(S + row * Xn);
    float4 v[8];
    float m = -1e30f;
#pragma unroll
    for (int i = 0; i < 8; i++) {
        v[i] = s4[t + i * 256];
        m = fmaxf(m, fmaxf(fmaxf(v[i].x, v[i].y), fmaxf(v[i].z, v[i].w)));
    }
    m = blockMax(m, red);
    float z = 0.f;
#pragma unroll
    for (int i = 0; i < 8; i++)
        z += __expf(v[i].x - m) + __expf(v[i].y - m) +
             __expf(v[i].z - m) + __expf(v[i].w - m);
    z = blockSum(z, red);
    // p < 0.0005  <=>  s < m + ln(0.0005 * Z)
    const float thr = m + __logf(0.0005f * z);
    float z2 = 0.f;
#pragma unroll
    for (int i = 0; i < 8; i++) {
        if (v[i].x >= thr) z2 += __expf(v[i].x - m);
        if (v[i].y >= thr) z2 += __expf(v[i].y - m);
        if (v[i].z >= thr) z2 += __expf(v[i].z - m);
        if (v[i].w >= thr) z2 += __expf(v[i].w - m);
    }
    z2 = blockSum(z2, red);
    const float inv = 1.f / z2;
    uint2* wo = reinterpret_cast<uint2*>(W + row * Xn);
#pragma unroll
    for (int i = 0; i < 8; i++) {
        float w0 = (v[i].x >= thr) ? __expf(v[i].x - m) * inv : 0.f;
        float w1 = (v[i].y >= thr) ? __expf(v[i].y - m) * inv : 0.f;
        float w2 = (v[i].z >= thr) ? __expf(v[i].z - m) * inv : 0.f;
        float w3 = (v[i].w >= thr) ? __expf(v[i].w - m) * inv : 0.f;
        __nv_bfloat162 lo = __floats2bfloat162_rn(w0, w1);
        __nv_bfloat162 hi = __floats2bfloat162_rn(w2, w3);
        uint2 pk;
        pk.x = *reinterpret_cast<uint32_t*>(&lo);
        pk.y = *reinterpret_cast<uint32_t*>(&hi);
        wo[t + i * 256] = pk;
    }
}

// ---------------- launch ----------------
extern "C" void kernel_launch(void* const* d_in, const int* in_sizes, int n_in,
                              void* d_out, int out_size)
{
    const float* feat  = (const float*)d_in[0];
    const float* mem_k = (const float*)d_in[1];
    const float* mem_v = (const float*)d_in[2];
    const float* mem_c = (const float*)d_in[3];
    // d_in[4] = mem_attn (unused by reference)
    const float* gq = (const float*)d_in[5];
    const float* bq = (const float*)d_in[6];
    const float* gk = (const float*)d_in[7];
    const float* bk = (const float*)d_in[8];
    const float* gv = (const float*)d_in[9];
    const float* bv = (const float*)d_in[10];
    float* out = (float*)d_out;

    bf16 *qh, *ql, *kh, *kl, *v, *vt, *W;
    float* S;
    cudaGetSymbolAddress((void**)&qh, g_qh);
    cudaGetSymbolAddress((void**)&ql, g_ql);
    cudaGetSymbolAddress((void**)&kh, g_kh);
    cudaGetSymbolAddress((void**)&kl, g_kl);
    cudaGetSymbolAddress((void**)&v,  g_v);
    cudaGetSymbolAddress((void**)&vt, g_vt);
    cudaGetSymbolAddress((void**)&S,  g_S);
    cudaGetSymbolAddress((void**)&W,  g_W);

    cudaFuncSetAttribute(gemm_kernel<0,1>, cudaFuncAttributeMaxDynamicSharedMemorySize, 65536);
    cudaFuncSetAttribute(gemm_kernel<1,0>, cudaFuncAttributeMaxDynamicSharedMemorySize, 65536);

    // LN with folds: q *= 1/sqrt(C); k *= mem_c (per row); v plain
    ln_kernel<<<Bn * Pn, 256>>>(feat,  qh, ql, gq, bq, nullptr, 1.f / 32.f);
    ln_kernel<<<Bn * Xn, 256>>>(mem_k, kh, kl, gk, bk, mem_c,   0.f);
    ln_kernel<<<Bn * Xn, 256>>>(mem_v, v, nullptr, gv, bv, nullptr, 1.f);

    transpose_kernel<<<dim3(Xn / 32, Cn / 32, Bn), dim3(32, 8)>>>(v, vt);

    // S = q @ k^T  (emulated fp32: qh*kh + qh*kl + ql*kh), scale+confidence folded
    gemm_kernel<0,1><<<dim3(Xn / 128, Pn / 128, Bn), 256, 65536>>>(
        qh, ql, kh, kl, S, nullptr, Pn, Xn, Cn);

    softmax_kernel<<<Bn * Pn, 256>>>(S, W);

    // out = W @ v^T + feat  (pure bf16)
    gemm_kernel<1,0><<<dim3(Cn / 128, Pn / 128, Bn), 256, 65536>>>(
        W, nullptr, vt, nullptr, out, feat, Pn, Cn, Xn);
}